// round 12
// baseline (speedup 1.0000x reference)
#include <cuda_runtime.h>
#include <cuda_fp16.h>
#include <cstdint>

// ---------------------------------------------------------------------------
// CrossAttention via fp16 mma.sync.m16n8k16 (fp32 accumulate) NT GEMMs.
// Round 12: 512 threads / 16 warps per CTA (4 per SMSP), warp tile 64x32,
// CTA tile 128x256x64, 3-stage cp.async. Tests the latency-bound hypothesis
// (ncu: tensor=37%, occ=12.5% at 8 warps/SM).
// ---------------------------------------------------------------------------

#define BATCH 8
#define L_Q   2048
#define L_KV  2048
#define D_Q   512
#define D_C   768
#define MKV   (BATCH * L_KV)   // 16384

// Scratch (device globals).
__device__ __align__(128) __half g_keyh [MKV * D_C];
__device__ __align__(128) __half g_valh [MKV * D_C];
__device__ __align__(128) __half g_qh   [BATCH * L_Q * D_Q];
__device__ __align__(128) __half g_wkT  [D_Q * D_C];
__device__ __align__(128) __half g_wvT  [D_Q * D_C];
__device__ __align__(128) __half g_woT  [D_Q * D_Q];
__device__ __align__(128) __half g_kproj[MKV * D_Q];
__device__ __align__(128) __half g_vprT [D_Q * MKV];              // [Dq][B*Lkv]
__device__ __align__(128) __half g_sc   [(size_t)BATCH * L_Q * L_KV]; // scores/probs
__device__ __align__(128) __half g_ctxh [BATCH * L_Q * D_Q];

// ---------------------------------------------------------------------------
// PTX helpers
// ---------------------------------------------------------------------------
__device__ __forceinline__ uint32_t smem_u32(const void* p) {
    uint32_t a;
    asm("{ .reg .u64 t; cvta.to.shared.u64 t, %1; cvt.u32.u64 %0, t; }"
        : "=r"(a) : "l"(p));
    return a;
}
__device__ __forceinline__ void cp16(uint32_t s, const void* g) {
    asm volatile("cp.async.cg.shared.global [%0], [%1], 16;" :: "r"(s), "l"(g));
}
#define CP_COMMIT()  asm volatile("cp.async.commit_group;")
#define CP_WAIT(n)   asm volatile("cp.async.wait_group %0;" :: "n"(n))

__device__ __forceinline__ void ldsm_x4(uint32_t r[4], uint32_t addr) {
    asm volatile("ldmatrix.sync.aligned.m8n8.x4.shared.b16 {%0,%1,%2,%3}, [%4];"
                 : "=r"(r[0]), "=r"(r[1]), "=r"(r[2]), "=r"(r[3]) : "r"(addr));
}
__device__ __forceinline__ void mma_f16(float c[4], const uint32_t a[4],
                                        uint32_t b0, uint32_t b1) {
    asm volatile(
        "mma.sync.aligned.m16n8k16.row.col.f32.f16.f16.f32 "
        "{%0,%1,%2,%3}, {%4,%5,%6,%7}, {%8,%9}, {%0,%1,%2,%3};"
        : "+f"(c[0]), "+f"(c[1]), "+f"(c[2]), "+f"(c[3])
        : "r"(a[0]), "r"(a[1]), "r"(a[2]), "r"(a[3]), "r"(b0), "r"(b1));
}

// ---------------------------------------------------------------------------
// fp16 NT GEMM: C[M,N] = A[M,K] @ B[N,K]^T (+ bias).
// BM=128, BN=256, BK=64. 512 threads (16 warps, 2x8), warp tile 64x32.
// Smem rows: 64 halves + 8 pad = 144B (ldsm/cp.async conflict-free).
// 3-stage cp.async pipeline. ~108 regs/thread -> no spills at 512 thr.
// OUT_HALF: write __half2; else fp32 float2.
// ROWBIAS: bias indexed by m-row; else by n-col.
// Requires M%128==0, N%256==0, K%64==0, K/64 >= 3.
// ---------------------------------------------------------------------------
#define HBM 128
#define HBN 256
#define HBK 64
#define ROWB 144
#define STG_A (128 * ROWB)             // 18432
#define STG_B (256 * ROWB)             // 36864
#define STG   (STG_A + STG_B)          // 55296
#define NSTAGE 3
#define SMEM_BYTES (NSTAGE * STG)      // 165888

template <bool OUT_HALF, bool ROWBIAS>
__global__ void __launch_bounds__(512, 1)
gemm_h(const __half* __restrict__ A, const __half* __restrict__ B,
       void* __restrict__ Cv, const float* __restrict__ bias,
       int M, int N, int K, int ldA, int ldB, int ldC,
       long sA, long sB, long sC)
{
    extern __shared__ char smem[];
    const uint32_t sbase = smem_u32(smem);

    const int tid  = threadIdx.x;
    const int lane = tid & 31;
    const int warp = tid >> 5;          // 0..15
    const int g = lane >> 2;
    const int t = lane & 3;
    const int mw = (warp >> 3) * 64;    // warp M offset (0,64)
    const int nw = (warp & 7) * 32;     // warp N offset (0..224)

    const int bm = blockIdx.y * HBM;
    const int bn = blockIdx.x * HBN;
    A += (long)blockIdx.z * sA;
    B += (long)blockIdx.z * sB;

    // Loader: 8 x 16B chunks per 128B row. A: 1024 chunks (2/thr),
    // B: 2048 chunks (4/thr), 512 threads.
    const int cu = tid & 7;             // chunk in row
    const int r0 = tid >> 3;            // 0..63

    const int nk = K / HBK;

    auto load_tile = [&](int kt) {
        const int s = kt % NSTAGE;
        const uint32_t as = sbase + s * STG;
        const uint32_t bs = as + STG_A;
        const long kof = (long)kt * HBK + cu * 8;
        #pragma unroll
        for (int i = 0; i < 2; i++) {
            const int r = r0 + 64 * i;
            cp16(as + r * ROWB + cu * 16, A + (long)(bm + r) * ldA + kof);
        }
        #pragma unroll
        for (int i = 0; i < 4; i++) {
            const int r = r0 + 64 * i;
            cp16(bs + r * ROWB + cu * 16, B + (long)(bn + r) * ldB + kof);
        }
        CP_COMMIT();
    };

    float acc[4][4][4];
    #pragma unroll
    for (int i = 0; i < 4; i++)
        #pragma unroll
        for (int j = 0; j < 4; j++)
            #pragma unroll
            for (int r = 0; r < 4; r++) acc[i][j][r] = 0.0f;

    load_tile(0);
    load_tile(1);

    const int lrow = lane & 15;
    const int lkb  = (lane >> 4) * 16;
    uint32_t aoff[4], boff[2];
    #pragma unroll
    for (int i = 0; i < 4; i++)  aoff[i]  = (mw + 16 * i + lrow) * ROWB + lkb;
    #pragma unroll
    for (int jj = 0; jj < 2; jj++) boff[jj] = (nw + 16 * jj + lrow) * ROWB + lkb;

    for (int kt = 0; kt < nk; kt++) {
        CP_WAIT(1);
        __syncthreads();                 // stage kt ready
        if (kt + 2 < nk) load_tile(kt + 2);

        const int s = kt % NSTAGE;
        const uint32_t as = sbase + s * STG;
        const uint32_t bs = as + STG_A;

        #pragma unroll
        for (int kh = 0; kh < 4; kh++) {          // 4 x k16
            uint32_t a[4][4], b[2][4];
            #pragma unroll
            for (int i = 0; i < 4; i++)  ldsm_x4(a[i], as + aoff[i] + kh * 32);
            #pragma unroll
            for (int jj = 0; jj < 2; jj++) ldsm_x4(b[jj], bs + boff[jj] + kh * 32);
            #pragma unroll
            for (int i = 0; i < 4; i++) {
                #pragma unroll
                for (int jj = 0; jj < 2; jj++) {
                    mma_f16(acc[i][2 * jj + 0], a[i], b[jj][0], b[jj][2]);
                    mma_f16(acc[i][2 * jj + 1], a[i], b[jj][1], b[jj][3]);
                }
            }
        }
        __syncthreads();                 // all warps done with stage buffer
    }

    // ----- epilogue -----
    #pragma unroll
    for (int i = 0; i < 4; i++) {
        const int r = bm + mw + 16 * i + g;
        float brow0 = 0.0f, brow1 = 0.0f;
        if (ROWBIAS && bias) { brow0 = bias[r]; brow1 = bias[r + 8]; }
        #pragma unroll
        for (int j = 0; j < 4; j++) {
            const int c = bn + nw + 8 * j + 2 * t;
            float bc0 = 0.0f, bc1 = 0.0f;
            if (!ROWBIAS && bias) { bc0 = bias[c]; bc1 = bias[c + 1]; }
            const float v00 = acc[i][j][0] + (ROWBIAS ? brow0 : bc0);
            const float v01 = acc[i][j][1] + (ROWBIAS ? brow0 : bc1);
            const float v10 = acc[i][j][2] + (ROWBIAS ? brow1 : bc0);
            const float v11 = acc[i][j][3] + (ROWBIAS ? brow1 : bc1);
            if (OUT_HALF) {
                __half* C = (__half*)Cv + (long)blockIdx.z * sC;
                *(__half2*)(C + (long)r * ldC + c)       = __floats2half2_rn(v00, v01);
                *(__half2*)(C + (long)(r + 8) * ldC + c) = __floats2half2_rn(v10, v11);
            } else {
                float* C = (float*)Cv + (long)blockIdx.z * sC;
                *(float2*)(C + (long)r * ldC + c)       = make_float2(v00, v01);
                *(float2*)(C + (long)(r + 8) * ldC + c) = make_float2(v10, v11);
            }
        }
    }
}

// ---------------------------------------------------------------------------
// Merged conversion: key, value, q (scaled). Grid-stride over 16B chunks.
// ---------------------------------------------------------------------------
__global__ void __launch_bounds__(256)
prep_convert(__half* __restrict__ keyh, const float* __restrict__ key,
             __half* __restrict__ valh, const float* __restrict__ value,
             __half* __restrict__ qh,   const float* __restrict__ query,
             int n8k, int n8q, float qscale)
{
    const int total = 2 * n8k + n8q;
    for (int i = blockIdx.x * blockDim.x + threadIdx.x; i < total;
         i += gridDim.x * blockDim.x) {
        const float* src; __half* dst; int idx; float sc;
        if (i < n8k)            { src = key;   dst = keyh; idx = i;           sc = 1.0f; }
        else if (i < 2 * n8k)   { src = value; dst = valh; idx = i - n8k;     sc = 1.0f; }
        else                    { src = query; dst = qh;   idx = i - 2 * n8k; sc = qscale; }
        float4 v0 = ((const float4*)src)[2 * idx];
        float4 v1 = ((const float4*)src)[2 * idx + 1];
        __half2 h[4];
        h[0] = __floats2half2_rn(v0.x * sc, v0.y * sc);
        h[1] = __floats2half2_rn(v0.z * sc, v0.w * sc);
        h[2] = __floats2half2_rn(v1.x * sc, v1.y * sc);
        h[3] = __floats2half2_rn(v1.z * sc, v1.w * sc);
        ((uint4*)dst)[idx] = *(uint4*)h;
    }
}

// ---------------------------------------------------------------------------
// Merged weight transposes: Wk,Wv [768,512] and Wo [512,512] -> [N,K] fp16.
// ---------------------------------------------------------------------------
__global__ void __launch_bounds__(256)
prep_transpose(__half* __restrict__ wkT, const float* __restrict__ Wk,
               __half* __restrict__ wvT, const float* __restrict__ Wv,
               __half* __restrict__ woT, const float* __restrict__ Wo)
{
    int b = blockIdx.x;
    const float* src; __half* dst; int K, N;
    if (b < 384)       { src = Wk; dst = wkT; K = D_C; N = D_Q; }
    else if (b < 768)  { src = Wv; dst = wvT; K = D_C; N = D_Q; b -= 384; }
    else               { src = Wo; dst = woT; K = D_Q; N = D_Q; b -= 768; }
    const int ntx = N / 32;
    const int n0 = (b % ntx) * 32;
    const int k0 = (b / ntx) * 32;

    __shared__ float tile[32][33];
    const int tx = threadIdx.x & 31;
    const int ty = threadIdx.x >> 5;
    #pragma unroll
    for (int i = 0; i < 32; i += 8)
        tile[ty + i][tx] = src[(long)(k0 + ty + i) * N + n0 + tx];
    __syncthreads();
    #pragma unroll
    for (int i = 0; i < 32; i += 8)
        dst[(long)(n0 + ty + i) * K + k0 + tx] = __float2half(tile[tx][ty + i]);
}

// ---------------------------------------------------------------------------
// In-place row softmax over 2048-length rows, fp16 in / fp16 out.
// ---------------------------------------------------------------------------
__global__ void __launch_bounds__(256)
softmax_h2048(__half* __restrict__ S)
{
    __half2* p = (__half2*)(S + (size_t)blockIdx.x * 2048);
    const int t = threadIdx.x;

    float v[8];
    #pragma unroll
    for (int i = 0; i < 4; i++) {
        float2 f = __half22float2(p[t + i * 256]);
        v[2 * i] = f.x; v[2 * i + 1] = f.y;
    }
    float mx = -1e30f;
    #pragma unroll
    for (int i = 0; i < 8; i++) mx = fmaxf(mx, v[i]);

    __shared__ float red[8];
    #pragma unroll
    for (int o = 16; o > 0; o >>= 1)
        mx = fmaxf(mx, __shfl_xor_sync(0xFFFFFFFFu, mx, o));
    if ((t & 31) == 0) red[t >> 5] = mx;
    __syncthreads();
    float rowmax = red[0];
    #pragma unroll
    for (int w = 1; w < 8; w++) rowmax = fmaxf(rowmax, red[w]);
    __syncthreads();

    float sum = 0.0f;
    #pragma unroll
    for (int i = 0; i < 8; i++) {
        v[i] = __expf(v[i] - rowmax);
        sum += v[i];
    }
    #pragma unroll
    for (int o = 16; o > 0; o >>= 1)
        sum += __shfl_xor_sync(0xFFFFFFFFu, sum, o);
    if ((t & 31) == 0) red[t >> 5] = sum;
    __syncthreads();
    float rowsum = 0.0f;
    #pragma unroll
    for (int w = 0; w < 8; w++) rowsum += red[w];

    const float inv = 1.0f / rowsum;
    #pragma unroll
    for (int i = 0; i < 4; i++)
        p[t + i * 256] = __floats2half2_rn(v[2 * i] * inv, v[2 * i + 1] * inv);
}

// ---------------------------------------------------------------------------
// Launcher
// ---------------------------------------------------------------------------
extern "C" void kernel_launch(void* const* d_in, const int* in_sizes, int n_in,
                              void* d_out, int out_size)
{
    const float* query = (const float*)d_in[0];
    const float* key   = (const float*)d_in[1];
    const float* value = (const float*)d_in[2];
    const float* Wk    = (const float*)d_in[3];
    const float* bk    = (const float*)d_in[4];
    const float* Wv    = (const float*)d_in[5];
    const float* bv    = (const float*)d_in[6];
    const float* Wo    = (const float*)d_in[7];
    const float* bo    = (const float*)d_in[8];
    float* out = (float*)d_out;

    __half *keyh, *valh, *qh, *wkT, *wvT, *woT, *kproj, *vprT, *sc, *ctxh;
    cudaGetSymbolAddress((void**)&keyh,  g_keyh);
    cudaGetSymbolAddress((void**)&valh,  g_valh);
    cudaGetSymbolAddress((void**)&qh,    g_qh);
    cudaGetSymbolAddress((void**)&wkT,   g_wkT);
    cudaGetSymbolAddress((void**)&wvT,   g_wvT);
    cudaGetSymbolAddress((void**)&woT,   g_woT);
    cudaGetSymbolAddress((void**)&kproj, g_kproj);
    cudaGetSymbolAddress((void**)&vprT,  g_vprT);
    cudaGetSymbolAddress((void**)&sc,    g_sc);
    cudaGetSymbolAddress((void**)&ctxh,  g_ctxh);

    static bool attr_done = false;
    if (!attr_done) {
        cudaFuncSetAttribute(gemm_h<true, false>,
                             cudaFuncAttributeMaxDynamicSharedMemorySize, SMEM_BYTES);
        cudaFuncSetAttribute(gemm_h<true, true>,
                             cudaFuncAttributeMaxDynamicSharedMemorySize, SMEM_BYTES);
        cudaFuncSetAttribute(gemm_h<false, false>,
                             cudaFuncAttributeMaxDynamicSharedMemorySize, SMEM_BYTES);
        attr_done = true;
    }

    const float scale = 1.0f / sqrtf((float)D_Q);

    // 0) merged prep: conversions (scale folded into Q) + weight transposes.
    prep_convert<<<2048, 256>>>(keyh, key, valh, value, qh, query,
                                MKV * D_C / 8, BATCH * L_Q * D_Q / 8, scale);
    prep_transpose<<<1024, 256>>>(wkT, Wk, wvT, Wv, woT, Wo);

    // 1) K projection: kproj[16384,512] = keyh @ wkT^T + bk (col bias), half out.
    gemm_h<true, false><<<dim3(D_Q / HBN, MKV / HBM, 1), 512, SMEM_BYTES>>>(
        keyh, wkT, kproj, bk, MKV, D_Q, D_C, D_C, D_C, D_Q, 0, 0, 0);

    // 2) V projection TRANSPOSED: vprT[512,16384] = wvT @ valh^T + bv (ROW bias).
    gemm_h<true, true><<<dim3(MKV / HBN, D_Q / HBM, 1), 512, SMEM_BYTES>>>(
        wvT, valh, vprT, bv, D_Q, MKV, D_C, D_C, D_C, MKV, 0, 0, 0);

    // 3) Scores per batch: qh_b[2048,512] @ kproj_b^T -> fp16 (scale pre-folded).
    gemm_h<true, false><<<dim3(L_KV / HBN, L_Q / HBM, BATCH), 512, SMEM_BYTES>>>(
        qh, kproj, sc, nullptr, L_Q, L_KV, D_Q, D_Q, D_Q, L_KV,
        (long)L_Q * D_Q, (long)L_KV * D_Q, (long)L_Q * L_KV);

    // 4) Softmax in place (fp16).
    softmax_h2048<<<BATCH * L_Q, 256>>>(sc);

    // 5) Context per batch: probs_b[2048,2048] @ (vprT[:, b])^T -> ctxh, half out.
    gemm_h<true, false><<<dim3(D_Q / HBN, L_Q / HBM, BATCH), 512, SMEM_BYTES>>>(
        sc, vprT, ctxh, nullptr, L_Q, D_Q, L_KV, L_KV, MKV, D_Q,
        (long)L_Q * L_KV, (long)L_KV, (long)L_Q * D_Q);

    // 6) Output projection: ctxh[16384,512] @ woT^T + bo -> fp32 out.
    gemm_h<false, false><<<dim3(D_Q / HBN, MKV / HBM, 1), 512, SMEM_BYTES>>>(
        ctxh, woT, out, bo, MKV, D_Q, D_Q, D_Q, D_Q, D_Q, 0, 0, 0);
}

// round 15
// speedup vs baseline: 1.0057x; 1.0057x over previous
#include <cuda_runtime.h>
#include <cuda_fp16.h>
#include <cstdint>

// ---------------------------------------------------------------------------
// CrossAttention via fp16 mma.sync.m16n8k16 (fp32 accumulate) NT GEMMs.
// Round 13: anti-wave-quantization tiling. N=512 GEMMs use 128x64 CTA tiles
// (1024-CTA grids, 1.2% tail vs 13.5%), 2 CTAs/SM. Scores keeps 128x256.
// ---------------------------------------------------------------------------

#define BATCH 8
#define L_Q   2048
#define L_KV  2048
#define D_Q   512
#define D_C   768
#define MKV   (BATCH * L_KV)   // 16384

// Scratch (device globals).
__device__ __align__(128) __half g_keyh [MKV * D_C];
__device__ __align__(128) __half g_valh [MKV * D_C];
__device__ __align__(128) __half g_qh   [BATCH * L_Q * D_Q];
__device__ __align__(128) __half g_wkT  [D_Q * D_C];
__device__ __align__(128) __half g_wvT  [D_Q * D_C];
__device__ __align__(128) __half g_woT  [D_Q * D_Q];
__device__ __align__(128) __half g_kproj[MKV * D_Q];
__device__ __align__(128) __half g_vprT [D_Q * MKV];              // [Dq][B*Lkv]
__device__ __align__(128) __half g_sc   [(size_t)BATCH * L_Q * L_KV]; // scores/probs
__device__ __align__(128) __half g_ctxh [BATCH * L_Q * D_Q];

// ---------------------------------------------------------------------------
// PTX helpers
// ---------------------------------------------------------------------------
__device__ __forceinline__ uint32_t smem_u32(const void* p) {
    uint32_t a;
    asm("{ .reg .u64 t; cvta.to.shared.u64 t, %1; cvt.u32.u64 %0, t; }"
        : "=r"(a) : "l"(p));
    return a;
}
__device__ __forceinline__ void cp16(uint32_t s, const void* g) {
    asm volatile("cp.async.cg.shared.global [%0], [%1], 16;" :: "r"(s), "l"(g));
}
#define CP_COMMIT()  asm volatile("cp.async.commit_group;")
#define CP_WAIT(n)   asm volatile("cp.async.wait_group %0;" :: "n"(n))

__device__ __forceinline__ void ldsm_x4(uint32_t r[4], uint32_t addr) {
    asm volatile("ldmatrix.sync.aligned.m8n8.x4.shared.b16 {%0,%1,%2,%3}, [%4];"
                 : "=r"(r[0]), "=r"(r[1]), "=r"(r[2]), "=r"(r[3]) : "r"(addr));
}
__device__ __forceinline__ void mma_f16(float c[4], const uint32_t a[4],
                                        uint32_t b0, uint32_t b1) {
    asm volatile(
        "mma.sync.aligned.m16n8k16.row.col.f32.f16.f16.f32 "
        "{%0,%1,%2,%3}, {%4,%5,%6,%7}, {%8,%9}, {%0,%1,%2,%3};"
        : "+f"(c[0]), "+f"(c[1]), "+f"(c[2]), "+f"(c[3])
        : "r"(a[0]), "r"(a[1]), "r"(a[2]), "r"(a[3]), "r"(b0), "r"(b1));
}

// ===========================================================================
// Kernel A (scores): BM=128, BN=256, BK=128, 256 thr (8 warps 2x4, 64x64).
// 2-stage cp.async, fragment double-buffering. (Round-11 winner, unchanged.)
// ===========================================================================
#define ROWB 272                       // bytes per smem row (136 halves)
#define A_STGA (128 * ROWB)            // 34816
#define A_STGB (256 * ROWB)            // 69632
#define A_STG  (A_STGA + A_STGB)       // 104448
#define A_SMEM (2 * A_STG)             // 208896

template <bool OUT_HALF, bool ROWBIAS>
__global__ void __launch_bounds__(256, 1)
gemm256(const __half* __restrict__ A, const __half* __restrict__ B,
        void* __restrict__ Cv, const float* __restrict__ bias,
        int M, int N, int K, int ldA, int ldB, int ldC,
        long sA, long sB, long sC)
{
    extern __shared__ char smem[];
    const uint32_t sbase = smem_u32(smem);

    const int tid  = threadIdx.x;
    const int lane = tid & 31;
    const int warp = tid >> 5;
    const int g = lane >> 2;
    const int t = lane & 3;
    const int mw = (warp >> 2) * 64;
    const int nw = (warp & 3) * 64;

    const int bm = blockIdx.y * 128;
    const int bn = blockIdx.x * 256;
    A += (long)blockIdx.z * sA;
    B += (long)blockIdx.z * sB;

    const int cu = tid & 15;
    const int r0 = tid >> 4;

    const int nk = K / 128;

    auto load_tile = [&](int kt) {
        const int s = kt & 1;
        const uint32_t as = sbase + s * A_STG;
        const uint32_t bs = as + A_STGA;
        const long kof = (long)kt * 128 + cu * 8;
        #pragma unroll
        for (int i = 0; i < 8; i++) {
            const int r = r0 + 16 * i;
            cp16(as + r * ROWB + cu * 16, A + (long)(bm + r) * ldA + kof);
        }
        #pragma unroll
        for (int i = 0; i < 16; i++) {
            const int r = r0 + 16 * i;
            cp16(bs + r * ROWB + cu * 16, B + (long)(bn + r) * ldB + kof);
        }
        CP_COMMIT();
    };

    float acc[4][8][4];
    #pragma unroll
    for (int i = 0; i < 4; i++)
        #pragma unroll
        for (int j = 0; j < 8; j++)
            #pragma unroll
            for (int r = 0; r < 4; r++) acc[i][j][r] = 0.0f;

    load_tile(0);

    const int lrow = lane & 15;
    const int lkb  = (lane >> 4) * 16;
    uint32_t aoff[4], boff[4];
    #pragma unroll
    for (int i = 0; i < 4; i++)  aoff[i]  = (mw + 16 * i + lrow) * ROWB + lkb;
    #pragma unroll
    for (int jj = 0; jj < 4; jj++) boff[jj] = (nw + 16 * jj + lrow) * ROWB + lkb;

    uint32_t a[2][4][4], b[2][4][4];

    for (int kt = 0; kt < nk; kt++) {
        if (kt + 1 < nk) { load_tile(kt + 1); CP_WAIT(1); }
        else             { CP_WAIT(0); }
        __syncthreads();

        const int s = kt & 1;
        const uint32_t as = sbase + s * A_STG;
        const uint32_t bs = as + A_STGA;

        #pragma unroll
        for (int i = 0; i < 4; i++)  ldsm_x4(a[0][i], as + aoff[i]);
        #pragma unroll
        for (int jj = 0; jj < 4; jj++) ldsm_x4(b[0][jj], bs + boff[jj]);

        #pragma unroll
        for (int kh = 0; kh < 8; kh++) {
            const int cur = kh & 1, nxt = cur ^ 1;
            if (kh < 7) {
                #pragma unroll
                for (int i = 0; i < 4; i++)
                    ldsm_x4(a[nxt][i], as + aoff[i] + (kh + 1) * 32);
                #pragma unroll
                for (int jj = 0; jj < 4; jj++)
                    ldsm_x4(b[nxt][jj], bs + boff[jj] + (kh + 1) * 32);
            }
            #pragma unroll
            for (int i = 0; i < 4; i++) {
                #pragma unroll
                for (int jj = 0; jj < 4; jj++) {
                    mma_f16(acc[i][2 * jj + 0], a[cur][i], b[cur][jj][0], b[cur][jj][2]);
                    mma_f16(acc[i][2 * jj + 1], a[cur][i], b[cur][jj][1], b[cur][jj][3]);
                }
            }
        }
        __syncthreads();
    }

    #pragma unroll
    for (int i = 0; i < 4; i++) {
        const int r = bm + mw + 16 * i + g;
        float brow0 = 0.0f, brow1 = 0.0f;
        if (ROWBIAS && bias) { brow0 = bias[r]; brow1 = bias[r + 8]; }
        #pragma unroll
        for (int j = 0; j < 8; j++) {
            const int c = bn + nw + 8 * j + 2 * t;
            float bc0 = 0.0f, bc1 = 0.0f;
            if (!ROWBIAS && bias) { bc0 = bias[c]; bc1 = bias[c + 1]; }
            const float v00 = acc[i][j][0] + (ROWBIAS ? brow0 : bc0);
            const float v01 = acc[i][j][1] + (ROWBIAS ? brow0 : bc1);
            const float v10 = acc[i][j][2] + (ROWBIAS ? brow1 : bc0);
            const float v11 = acc[i][j][3] + (ROWBIAS ? brow1 : bc1);
            if (OUT_HALF) {
                __half* C = (__half*)Cv + (long)blockIdx.z * sC;
                *(__half2*)(C + (long)r * ldC + c)       = __floats2half2_rn(v00, v01);
                *(__half2*)(C + (long)(r + 8) * ldC + c) = __floats2half2_rn(v10, v11);
            } else {
                float* C = (float*)Cv + (long)blockIdx.z * sC;
                *(float2*)(C + (long)r * ldC + c)       = make_float2(v00, v01);
                *(float2*)(C + (long)(r + 8) * ldC + c) = make_float2(v10, v11);
            }
        }
    }
}

// ===========================================================================
// Kernel B (narrow N): BM=128, BN=64, BK=128, 128 thr (4 warps 2x2, 64x32).
// 2-stage cp.async, 2 CTAs/SM. Grids of 1024 CTAs -> 1.2% wave tail.
// ===========================================================================
#define B_STGA (128 * ROWB)            // 34816
#define B_STGB (64 * ROWB)             // 17408
#define B_STG  (B_STGA + B_STGB)       // 52224
#define B_SMEM (2 * B_STG)             // 104448

template <bool OUT_HALF, bool ROWBIAS>
__global__ void __launch_bounds__(128, 2)
gemm64(const __half* __restrict__ A, const __half* __restrict__ B,
       void* __restrict__ Cv, const float* __restrict__ bias,
       int M, int N, int K, int ldA, int ldB, int ldC,
       long sA, long sB, long sC)
{
    extern __shared__ char smem[];
    const uint32_t sbase = smem_u32(smem);

    const int tid  = threadIdx.x;
    const int lane = tid & 31;
    const int warp = tid >> 5;          // 0..3
    const int g = lane >> 2;
    const int t = lane & 3;
    const int mw = (warp >> 1) * 64;    // 0,64
    const int nw = (warp & 1) * 32;     // 0,32

    const int bm = blockIdx.y * 128;
    const int bn = blockIdx.x * 64;
    A += (long)blockIdx.z * sA;
    B += (long)blockIdx.z * sB;

    // Loader: 16 x 16B chunks per 256B row, 128 threads.
    const int cu = tid & 15;            // chunk in row
    const int r0 = tid >> 4;            // 0..7

    const int nk = K / 128;

    auto load_tile = [&](int kt) {
        const int s = kt & 1;
        const uint32_t as = sbase + s * B_STG;
        const uint32_t bs = as + B_STGA;
        const long kof = (long)kt * 128 + cu * 8;
        #pragma unroll
        for (int i = 0; i < 16; i++) {
            const int r = r0 + 8 * i;
            cp16(as + r * ROWB + cu * 16, A + (long)(bm + r) * ldA + kof);
        }
        #pragma unroll
        for (int i = 0; i < 8; i++) {
            const int r = r0 + 8 * i;
            cp16(bs + r * ROWB + cu * 16, B + (long)(bn + r) * ldB + kof);
        }
        CP_COMMIT();
    };

    float acc[4][4][4];
    #pragma unroll
    for (int i = 0; i < 4; i++)
        #pragma unroll
        for (int j = 0; j < 4; j++)
            #pragma unroll
            for (int r = 0; r < 4; r++) acc[i][j][r] = 0.0f;

    load_tile(0);

    const int lrow = lane & 15;
    const int lkb  = (lane >> 4) * 16;
    uint32_t aoff[4], boff[2];
    #pragma unroll
    for (int i = 0; i < 4; i++)  aoff[i]  = (mw + 16 * i + lrow) * ROWB + lkb;
    #pragma unroll
    for (int jj = 0; jj < 2; jj++) boff[jj] = (nw + 16 * jj + lrow) * ROWB + lkb;

    for (int kt = 0; kt < nk; kt++) {
        if (kt + 1 < nk) { load_tile(kt + 1); CP_WAIT(1); }
        else             { CP_WAIT(0); }
        __syncthreads();

        const int s = kt & 1;
        const uint32_t as = sbase + s * B_STG;
        const uint32_t bs = as + B_STGA;

        #pragma unroll
        for (int kh = 0; kh < 8; kh++) {
            uint32_t a[4][4], b[2][4];
            #pragma unroll
            for (int i = 0; i < 4; i++)  ldsm_x4(a[i], as + aoff[i] + kh * 32);
            #pragma unroll
            for (int jj = 0; jj < 2; jj++) ldsm_x4(b[jj], bs + boff[jj] + kh * 32);
            #pragma unroll
            for (int i = 0; i < 4; i++) {
                #pragma unroll
                for (int jj = 0; jj < 2; jj++) {
                    mma_f16(acc[i][2 * jj + 0], a[i], b[jj][0], b[jj][2]);
                    mma_f16(acc[i][2 * jj + 1], a[i], b[jj][1], b[jj][3]);
                }
            }
        }
        __syncthreads();
    }

    #pragma unroll
    for (int i = 0; i < 4; i++) {
        const int r = bm + mw + 16 * i + g;
        float brow0 = 0.0f, brow1 = 0.0f;
        if (ROWBIAS && bias) { brow0 = bias[r]; brow1 = bias[r + 8]; }
        #pragma unroll
        for (int j = 0; j < 4; j++) {
            const int c = bn + nw + 8 * j + 2 * t;
            float bc0 = 0.0f, bc1 = 0.0f;
            if (!ROWBIAS && bias) { bc0 = bias[c]; bc1 = bias[c + 1]; }
            const float v00 = acc[i][j][0] + (ROWBIAS ? brow0 : bc0);
            const float v01 = acc[i][j][1] + (ROWBIAS ? brow0 : bc1);
            const float v10 = acc[i][j][2] + (ROWBIAS ? brow1 : bc0);
            const float v11 = acc[i][j][3] + (ROWBIAS ? brow1 : bc1);
            if (OUT_HALF) {
                __half* C = (__half*)Cv + (long)blockIdx.z * sC;
                *(__half2*)(C + (long)r * ldC + c)       = __floats2half2_rn(v00, v01);
                *(__half2*)(C + (long)(r + 8) * ldC + c) = __floats2half2_rn(v10, v11);
            } else {
                float* C = (float*)Cv + (long)blockIdx.z * sC;
                *(float2*)(C + (long)r * ldC + c)       = make_float2(v00, v01);
                *(float2*)(C + (long)(r + 8) * ldC + c) = make_float2(v10, v11);
            }
        }
    }
}

// ---------------------------------------------------------------------------
// Merged conversion: key, value, q (scaled). Grid-stride over 16B chunks.
// ---------------------------------------------------------------------------
__global__ void __launch_bounds__(256)
prep_convert(__half* __restrict__ keyh, const float* __restrict__ key,
             __half* __restrict__ valh, const float* __restrict__ value,
             __half* __restrict__ qh,   const float* __restrict__ query,
             int n8k, int n8q, float qscale)
{
    const int total = 2 * n8k + n8q;
    for (int i = blockIdx.x * blockDim.x + threadIdx.x; i < total;
         i += gridDim.x * blockDim.x) {
        const float* src; __half* dst; int idx; float sc;
        if (i < n8k)            { src = key;   dst = keyh; idx = i;           sc = 1.0f; }
        else if (i < 2 * n8k)   { src = value; dst = valh; idx = i - n8k;     sc = 1.0f; }
        else                    { src = query; dst = qh;   idx = i - 2 * n8k; sc = qscale; }
        float4 v0 = ((const float4*)src)[2 * idx];
        float4 v1 = ((const float4*)src)[2 * idx + 1];
        __half2 h[4];
        h[0] = __floats2half2_rn(v0.x * sc, v0.y * sc);
        h[1] = __floats2half2_rn(v0.z * sc, v0.w * sc);
        h[2] = __floats2half2_rn(v1.x * sc, v1.y * sc);
        h[3] = __floats2half2_rn(v1.z * sc, v1.w * sc);
        ((uint4*)dst)[idx] = *(uint4*)h;
    }
}

// ---------------------------------------------------------------------------
// Merged weight transposes: Wk,Wv [768,512] and Wo [512,512] -> [N,K] fp16.
// ---------------------------------------------------------------------------
__global__ void __launch_bounds__(256)
prep_transpose(__half* __restrict__ wkT, const float* __restrict__ Wk,
               __half* __restrict__ wvT, const float* __restrict__ Wv,
               __half* __restrict__ woT, const float* __restrict__ Wo)
{
    int b = blockIdx.x;
    const float* src; __half* dst; int K, N;
    if (b < 384)       { src = Wk; dst = wkT; K = D_C; N = D_Q; }
    else if (b < 768)  { src = Wv; dst = wvT; K = D_C; N = D_Q; b -= 384; }
    else               { src = Wo; dst = woT; K = D_Q; N = D_Q; b -= 768; }
    const int ntx = N / 32;
    const int n0 = (b % ntx) * 32;
    const int k0 = (b / ntx) * 32;

    __shared__ float tile[32][33];
    const int tx = threadIdx.x & 31;
    const int ty = threadIdx.x >> 5;
    #pragma unroll
    for (int i = 0; i < 32; i += 8)
        tile[ty + i][tx] = src[(long)(k0 + ty + i) * N + n0 + tx];
    __syncthreads();
    #pragma unroll
    for (int i = 0; i < 32; i += 8)
        dst[(long)(n0 + ty + i) * K + k0 + tx] = __float2half(tile[tx][ty + i]);
}

// ---------------------------------------------------------------------------
// In-place row softmax over 2048-length rows, fp16 in / fp16 out.
// ---------------------------------------------------------------------------
__global__ void __launch_bounds__(256)
softmax_h2048(__half* __restrict__ S)
{
    __half2* p = (__half2*)(S + (size_t)blockIdx.x * 2048);
    const int t = threadIdx.x;

    float v[8];
    #pragma unroll
    for (int i = 0; i < 4; i++) {
        float2 f = __half22float2(p[t + i * 256]);
        v[2 * i] = f.x; v[2 * i + 1] = f.y;
    }
    float mx = -1e30f;
    #pragma unroll
    for (int i = 0; i < 8; i++) mx = fmaxf(mx, v[i]);

    __shared__ float red[8];
    #pragma unroll
    for (int o = 16; o > 0; o >>= 1)
        mx = fmaxf(mx, __shfl_xor_sync(0xFFFFFFFFu, mx, o));
    if ((t & 31) == 0) red[t >> 5] = mx;
    __syncthreads();
    float rowmax = red[0];
    #pragma unroll
    for (int w = 1; w < 8; w++) rowmax = fmaxf(rowmax, red[w]);
    __syncthreads();

    float sum = 0.0f;
    #pragma unroll
    for (int i = 0; i < 8; i++) {
        v[i] = __expf(v[i] - rowmax);
        sum += v[i];
    }
    #pragma unroll
    for (int o = 16; o > 0; o >>= 1)
        sum += __shfl_xor_sync(0xFFFFFFFFu, sum, o);
    if ((t & 31) == 0) red[t >> 5] = sum;
    __syncthreads();
    float rowsum = 0.0f;
    #pragma unroll
    for (int w = 0; w < 8; w++) rowsum += red[w];

    const float inv = 1.0f / rowsum;
    #pragma unroll
    for (int i = 0; i < 4; i++)
        p[t + i * 256] = __floats2half2_rn(v[2 * i] * inv, v[2 * i + 1] * inv);
}

// ---------------------------------------------------------------------------
// Launcher
// ---------------------------------------------------------------------------
extern "C" void kernel_launch(void* const* d_in, const int* in_sizes, int n_in,
                              void* d_out, int out_size)
{
    const float* query = (const float*)d_in[0];
    const float* key   = (const float*)d_in[1];
    const float* value = (const float*)d_in[2];
    const float* Wk    = (const float*)d_in[3];
    const float* bk    = (const float*)d_in[4];
    const float* Wv    = (const float*)d_in[5];
    const float* bv    = (const float*)d_in[6];
    const float* Wo    = (const float*)d_in[7];
    const float* bo    = (const float*)d_in[8];
    float* out = (float*)d_out;

    __half *keyh, *valh, *qh, *wkT, *wvT, *woT, *kproj, *vprT, *sc, *ctxh;
    cudaGetSymbolAddress((void**)&keyh,  g_keyh);
    cudaGetSymbolAddress((void**)&valh,  g_valh);
    cudaGetSymbolAddress((void**)&qh,    g_qh);
    cudaGetSymbolAddress((void**)&wkT,   g_wkT);
    cudaGetSymbolAddress((void**)&wvT,   g_wvT);
    cudaGetSymbolAddress((void**)&woT,   g_woT);
    cudaGetSymbolAddress((void**)&kproj, g_kproj);
    cudaGetSymbolAddress((void**)&vprT,  g_vprT);
    cudaGetSymbolAddress((void**)&sc,    g_sc);
    cudaGetSymbolAddress((void**)&ctxh,  g_ctxh);

    static bool attr_done = false;
    if (!attr_done) {
        cudaFuncSetAttribute(gemm256<true, false>,
                             cudaFuncAttributeMaxDynamicSharedMemorySize, A_SMEM);
        cudaFuncSetAttribute(gemm64<true, false>,
                             cudaFuncAttributeMaxDynamicSharedMemorySize, B_SMEM);
        cudaFuncSetAttribute(gemm64<true, true>,
                             cudaFuncAttributeMaxDynamicSharedMemorySize, B_SMEM);
        cudaFuncSetAttribute(gemm64<false, false>,
                             cudaFuncAttributeMaxDynamicSharedMemorySize, B_SMEM);
        attr_done = true;
    }

    const float scale = 1.0f / sqrtf((float)D_Q);

    // 0) merged prep: conversions (scale folded into Q) + weight transposes.
    prep_convert<<<2048, 256>>>(keyh, key, valh, value, qh, query,
                                MKV * D_C / 8, BATCH * L_Q * D_Q / 8, scale);
    prep_transpose<<<1024, 256>>>(wkT, Wk, wvT, Wv, woT, Wo);

    // 1) K projection: kproj[16384,512] = keyh @ wkT^T + bk. 1024 CTAs.
    gemm64<true, false><<<dim3(D_Q / 64, MKV / 128, 1), 128, B_SMEM>>>(
        keyh, wkT, kproj, bk, MKV, D_Q, D_C, D_C, D_C, D_Q, 0, 0, 0);

    // 2) V projection TRANSPOSED: vprT[512,16384] = wvT @ valh^T + bv (ROW bias).
    //    1024 CTAs (256 x 4).
    gemm64<true, true><<<dim3(MKV / 64, D_Q / 128, 1), 128, B_SMEM>>>(
        wvT, valh, vprT, bv, D_Q, MKV, D_C, D_C, D_C, MKV, 0, 0, 0);

    // 3) Scores per batch: qh_b[2048,512] @ kproj_b^T -> fp16. 1024 CTAs.
    gemm256<true, false><<<dim3(L_KV / 256, L_Q / 128, BATCH), 256, A_SMEM>>>(
        qh, kproj, sc, nullptr, L_Q, L_KV, D_Q, D_Q, D_Q, L_KV,
        (long)L_Q * D_Q, (long)L_KV * D_Q, (long)L_Q * L_KV);

    // 4) Softmax in place (fp16).
    softmax_h2048<<<BATCH * L_Q, 256>>>(sc);

    // 5) Context per batch: probs_b[2048,2048] @ (vprT[:, b])^T -> ctxh. 1024 CTAs.
    gemm64<true, false><<<dim3(D_Q / 64, L_Q / 128, BATCH), 128, B_SMEM>>>(
        sc, vprT, ctxh, nullptr, L_Q, D_Q, L_KV, L_KV, MKV, D_Q,
        (long)L_Q * L_KV, (long)L_KV, (long)L_Q * D_Q);

    // 6) Output projection: ctxh[16384,512] @ woT^T + bo -> fp32 out. 1024 CTAs.
    gemm64<false, false><<<dim3(D_Q / 64, MKV / 128, 1), 128, B_SMEM>>>(
        ctxh, woT, out, bo, MKV, D_Q, D_Q, D_Q, D_Q, D_Q, 0, 0, 0);
}

// round 16
// speedup vs baseline: 1.0362x; 1.0303x over previous
#include <cuda_runtime.h>
#include <cuda_fp16.h>
#include <cstdint>

// ---------------------------------------------------------------------------
// CrossAttention via fp16 mma.sync.m16n8k16 (fp32 accumulate) NT GEMMs.
// Round 16: output projection algebraically folded into the V projection:
//   out = P@(V@(Wv@Wo) + 1*(Wo^T bv)^T) + bo
// Removes the 17.2-GFLOP outproj GEMM + ctx round-trip. GEMM engine = round-11
// winner (BM128/BN256/BK128, 256 thr, 2-stage cp.async, frag double-buffer).
// ---------------------------------------------------------------------------

#define BATCH 8
#define L_Q   2048
#define L_KV  2048
#define D_Q   512
#define D_C   768
#define MKV   (BATCH * L_KV)   // 16384

// Scratch (device globals).
__device__ __align__(128) __half g_keyh [MKV * D_C];
__device__ __align__(128) __half g_valh [MKV * D_C];
__device__ __align__(128) __half g_qh   [BATCH * L_Q * D_Q];
__device__ __align__(128) __half g_wvh  [D_C * D_Q];              // Wv fp16 (row-major)
__device__ __align__(128) __half g_wkT  [D_Q * D_C];
__device__ __align__(128) __half g_woT  [D_Q * D_Q];
__device__ __align__(128) __half g_wvoT [D_Q * D_C];              // (Wv@Wo)^T
__device__ __align__(128) float  g_bvo  [D_Q];                    // Wo^T bv
__device__ __align__(128) __half g_kproj[MKV * D_Q];
__device__ __align__(128) __half g_vprT2[D_Q * MKV];              // (V@Wvo + bvo)^T
__device__ __align__(128) __half g_sc   [(size_t)BATCH * L_Q * L_KV]; // scores/probs

// ---------------------------------------------------------------------------
// PTX helpers
// ---------------------------------------------------------------------------
__device__ __forceinline__ uint32_t smem_u32(const void* p) {
    uint32_t a;
    asm("{ .reg .u64 t; cvta.to.shared.u64 t, %1; cvt.u32.u64 %0, t; }"
        : "=r"(a) : "l"(p));
    return a;
}
__device__ __forceinline__ void cp16(uint32_t s, const void* g) {
    asm volatile("cp.async.cg.shared.global [%0], [%1], 16;" :: "r"(s), "l"(g));
}
#define CP_COMMIT()  asm volatile("cp.async.commit_group;")
#define CP_WAIT(n)   asm volatile("cp.async.wait_group %0;" :: "n"(n))

__device__ __forceinline__ void ldsm_x4(uint32_t r[4], uint32_t addr) {
    asm volatile("ldmatrix.sync.aligned.m8n8.x4.shared.b16 {%0,%1,%2,%3}, [%4];"
                 : "=r"(r[0]), "=r"(r[1]), "=r"(r[2]), "=r"(r[3]) : "r"(addr));
}
__device__ __forceinline__ void mma_f16(float c[4], const uint32_t a[4],
                                        uint32_t b0, uint32_t b1) {
    asm volatile(
        "mma.sync.aligned.m16n8k16.row.col.f32.f16.f16.f32 "
        "{%0,%1,%2,%3}, {%4,%5,%6,%7}, {%8,%9}, {%0,%1,%2,%3};"
        : "+f"(c[0]), "+f"(c[1]), "+f"(c[2]), "+f"(c[3])
        : "r"(a[0]), "r"(a[1]), "r"(a[2]), "r"(a[3]), "r"(b0), "r"(b1));
}

// ===========================================================================
// NT GEMM: C[M,N] = A[M,K] @ B[N,K]^T (+ bias).
// BM=128, BN=256, BK=128, 256 thr (8 warps 2x4, warp tile 64x64).
// 2-stage cp.async (204KB smem), fragment double-buffering.
// Requires M%128==0, N%256==0, K%128==0.
// ===========================================================================
#define ROWB 272                       // bytes per smem row (136 halves)
#define A_STGA (128 * ROWB)            // 34816
#define A_STGB (256 * ROWB)            // 69632
#define A_STG  (A_STGA + A_STGB)       // 104448
#define A_SMEM (2 * A_STG)             // 208896

template <bool OUT_HALF, bool ROWBIAS>
__global__ void __launch_bounds__(256, 1)
gemm256(const __half* __restrict__ A, const __half* __restrict__ B,
        void* __restrict__ Cv, const float* __restrict__ bias,
        int M, int N, int K, int ldA, int ldB, int ldC,
        long sA, long sB, long sC)
{
    extern __shared__ char smem[];
    const uint32_t sbase = smem_u32(smem);

    const int tid  = threadIdx.x;
    const int lane = tid & 31;
    const int warp = tid >> 5;
    const int g = lane >> 2;
    const int t = lane & 3;
    const int mw = (warp >> 2) * 64;
    const int nw = (warp & 3) * 64;

    const int bm = blockIdx.y * 128;
    const int bn = blockIdx.x * 256;
    A += (long)blockIdx.z * sA;
    B += (long)blockIdx.z * sB;

    const int cu = tid & 15;
    const int r0 = tid >> 4;

    const int nk = K / 128;

    auto load_tile = [&](int kt) {
        const int s = kt & 1;
        const uint32_t as = sbase + s * A_STG;
        const uint32_t bs = as + A_STGA;
        const long kof = (long)kt * 128 + cu * 8;
        #pragma unroll
        for (int i = 0; i < 8; i++) {
            const int r = r0 + 16 * i;
            cp16(as + r * ROWB + cu * 16, A + (long)(bm + r) * ldA + kof);
        }
        #pragma unroll
        for (int i = 0; i < 16; i++) {
            const int r = r0 + 16 * i;
            cp16(bs + r * ROWB + cu * 16, B + (long)(bn + r) * ldB + kof);
        }
        CP_COMMIT();
    };

    float acc[4][8][4];
    #pragma unroll
    for (int i = 0; i < 4; i++)
        #pragma unroll
        for (int j = 0; j < 8; j++)
            #pragma unroll
            for (int r = 0; r < 4; r++) acc[i][j][r] = 0.0f;

    load_tile(0);

    const int lrow = lane & 15;
    const int lkb  = (lane >> 4) * 16;
    uint32_t aoff[4], boff[4];
    #pragma unroll
    for (int i = 0; i < 4; i++)  aoff[i]  = (mw + 16 * i + lrow) * ROWB + lkb;
    #pragma unroll
    for (int jj = 0; jj < 4; jj++) boff[jj] = (nw + 16 * jj + lrow) * ROWB + lkb;

    uint32_t a[2][4][4], b[2][4][4];

    for (int kt = 0; kt < nk; kt++) {
        if (kt + 1 < nk) { load_tile(kt + 1); CP_WAIT(1); }
        else             { CP_WAIT(0); }
        __syncthreads();

        const int s = kt & 1;
        const uint32_t as = sbase + s * A_STG;
        const uint32_t bs = as + A_STGA;

        #pragma unroll
        for (int i = 0; i < 4; i++)  ldsm_x4(a[0][i], as + aoff[i]);
        #pragma unroll
        for (int jj = 0; jj < 4; jj++) ldsm_x4(b[0][jj], bs + boff[jj]);

        #pragma unroll
        for (int kh = 0; kh < 8; kh++) {
            const int cur = kh & 1, nxt = cur ^ 1;
            if (kh < 7) {
                #pragma unroll
                for (int i = 0; i < 4; i++)
                    ldsm_x4(a[nxt][i], as + aoff[i] + (kh + 1) * 32);
                #pragma unroll
                for (int jj = 0; jj < 4; jj++)
                    ldsm_x4(b[nxt][jj], bs + boff[jj] + (kh + 1) * 32);
            }
            #pragma unroll
            for (int i = 0; i < 4; i++) {
                #pragma unroll
                for (int jj = 0; jj < 4; jj++) {
                    mma_f16(acc[i][2 * jj + 0], a[cur][i], b[cur][jj][0], b[cur][jj][2]);
                    mma_f16(acc[i][2 * jj + 1], a[cur][i], b[cur][jj][1], b[cur][jj][3]);
                }
            }
        }
        __syncthreads();
    }

    #pragma unroll
    for (int i = 0; i < 4; i++) {
        const int r = bm + mw + 16 * i + g;
        float brow0 = 0.0f, brow1 = 0.0f;
        if (ROWBIAS && bias) { brow0 = bias[r]; brow1 = bias[r + 8]; }
        #pragma unroll
        for (int j = 0; j < 8; j++) {
            const int c = bn + nw + 8 * j + 2 * t;
            float bc0 = 0.0f, bc1 = 0.0f;
            if (!ROWBIAS && bias) { bc0 = bias[c]; bc1 = bias[c + 1]; }
            const float v00 = acc[i][j][0] + (ROWBIAS ? brow0 : bc0);
            const float v01 = acc[i][j][1] + (ROWBIAS ? brow0 : bc1);
            const float v10 = acc[i][j][2] + (ROWBIAS ? brow1 : bc0);
            const float v11 = acc[i][j][3] + (ROWBIAS ? brow1 : bc1);
            if (OUT_HALF) {
                __half* C = (__half*)Cv + (long)blockIdx.z * sC;
                *(__half2*)(C + (long)r * ldC + c)       = __floats2half2_rn(v00, v01);
                *(__half2*)(C + (long)(r + 8) * ldC + c) = __floats2half2_rn(v10, v11);
            } else {
                float* C = (float*)Cv + (long)blockIdx.z * sC;
                *(float2*)(C + (long)r * ldC + c)       = make_float2(v00, v01);
                *(float2*)(C + (long)(r + 8) * ldC + c) = make_float2(v10, v11);
            }
        }
    }
}

// ---------------------------------------------------------------------------
// Merged conversion: key, value, q (scaled), Wv. Grid-stride over 16B chunks.
// ---------------------------------------------------------------------------
__global__ void __launch_bounds__(256)
prep_convert(__half* __restrict__ keyh, const float* __restrict__ key,
             __half* __restrict__ valh, const float* __restrict__ value,
             __half* __restrict__ qh,   const float* __restrict__ query,
             __half* __restrict__ wvh,  const float* __restrict__ Wv,
             int n8k, int n8q, int n8w, float qscale)
{
    const int total = 2 * n8k + n8q + n8w;
    for (int i = blockIdx.x * blockDim.x + threadIdx.x; i < total;
         i += gridDim.x * blockDim.x) {
        const float* src; __half* dst; int idx; float sc = 1.0f;
        if (i < n8k)                  { src = key;   dst = keyh; idx = i; }
        else if (i < 2 * n8k)         { src = value; dst = valh; idx = i - n8k; }
        else if (i < 2 * n8k + n8q)   { src = query; dst = qh;   idx = i - 2 * n8k; sc = qscale; }
        else                          { src = Wv;    dst = wvh;  idx = i - 2 * n8k - n8q; }
        float4 v0 = ((const float4*)src)[2 * idx];
        float4 v1 = ((const float4*)src)[2 * idx + 1];
        __half2 h[4];
        h[0] = __floats2half2_rn(v0.x * sc, v0.y * sc);
        h[1] = __floats2half2_rn(v0.z * sc, v0.w * sc);
        h[2] = __floats2half2_rn(v1.x * sc, v1.y * sc);
        h[3] = __floats2half2_rn(v1.z * sc, v1.w * sc);
        ((uint4*)dst)[idx] = *(uint4*)h;
    }
}

// ---------------------------------------------------------------------------
// Merged weight transposes: Wk[768,512]->wkT[512,768], Wo[512,512]->woT.
// Plus bvo[n] = sum_d bv[d]*Wo[d][n] (blocks 640..641).
// ---------------------------------------------------------------------------
__global__ void __launch_bounds__(256)
prep_transpose(__half* __restrict__ wkT, const float* __restrict__ Wk,
               __half* __restrict__ woT, const float* __restrict__ Wo,
               float* __restrict__ bvo,  const float* __restrict__ bv)
{
    int b = blockIdx.x;
    if (b >= 640) {            // bvo: 2 blocks x 256 threads = 512 outputs
        const int n = (b - 640) * 256 + threadIdx.x;
        float s = 0.0f;
        for (int d = 0; d < D_Q; d++)
            s += bv[d] * Wo[(long)d * D_Q + n];
        bvo[n] = s;
        return;
    }
    const float* src; __half* dst; int K, N;
    if (b < 384)       { src = Wk; dst = wkT; K = D_C; N = D_Q; }
    else               { src = Wo; dst = woT; K = D_Q; N = D_Q; b -= 384; }
    const int ntx = N / 32;
    const int n0 = (b % ntx) * 32;
    const int k0 = (b / ntx) * 32;

    __shared__ float tile[32][33];
    const int tx = threadIdx.x & 31;
    const int ty = threadIdx.x >> 5;
    #pragma unroll
    for (int i = 0; i < 32; i += 8)
        tile[ty + i][tx] = src[(long)(k0 + ty + i) * N + n0 + tx];
    __syncthreads();
    #pragma unroll
    for (int i = 0; i < 32; i += 8)
        dst[(long)(n0 + ty + i) * K + k0 + tx] = __float2half(tile[tx][ty + i]);
}

// ---------------------------------------------------------------------------
// In-place row softmax over 2048-length rows, fp16 in / fp16 out.
// ---------------------------------------------------------------------------
__global__ void __launch_bounds__(256)
softmax_h2048(__half* __restrict__ S)
{
    __half2* p = (__half2*)(S + (size_t)blockIdx.x * 2048);
    const int t = threadIdx.x;

    float v[8];
    #pragma unroll
    for (int i = 0; i < 4; i++) {
        float2 f = __half22float2(p[t + i * 256]);
        v[2 * i] = f.x; v[2 * i + 1] = f.y;
    }
    float mx = -1e30f;
    #pragma unroll
    for (int i = 0; i < 8; i++) mx = fmaxf(mx, v[i]);

    __shared__ float red[8];
    #pragma unroll
    for (int o = 16; o > 0; o >>= 1)
        mx = fmaxf(mx, __shfl_xor_sync(0xFFFFFFFFu, mx, o));
    if ((t & 31) == 0) red[t >> 5] = mx;
    __syncthreads();
    float rowmax = red[0];
    #pragma unroll
    for (int w = 1; w < 8; w++) rowmax = fmaxf(rowmax, red[w]);
    __syncthreads();

    float sum = 0.0f;
    #pragma unroll
    for (int i = 0; i < 8; i++) {
        v[i] = __expf(v[i] - rowmax);
        sum += v[i];
    }
    #pragma unroll
    for (int o = 16; o > 0; o >>= 1)
        sum += __shfl_xor_sync(0xFFFFFFFFu, sum, o);
    if ((t & 31) == 0) red[t >> 5] = sum;
    __syncthreads();
    float rowsum = 0.0f;
    #pragma unroll
    for (int w = 0; w < 8; w++) rowsum += red[w];

    const float inv = 1.0f / rowsum;
    #pragma unroll
    for (int i = 0; i < 4; i++)
        p[t + i * 256] = __floats2half2_rn(v[2 * i] * inv, v[2 * i + 1] * inv);
}

// ---------------------------------------------------------------------------
// Launcher
// ---------------------------------------------------------------------------
extern "C" void kernel_launch(void* const* d_in, const int* in_sizes, int n_in,
                              void* d_out, int out_size)
{
    const float* query = (const float*)d_in[0];
    const float* key   = (const float*)d_in[1];
    const float* value = (const float*)d_in[2];
    const float* Wk    = (const float*)d_in[3];
    const float* bk    = (const float*)d_in[4];
    const float* Wv    = (const float*)d_in[5];
    const float* bv    = (const float*)d_in[6];
    const float* Wo    = (const float*)d_in[7];
    const float* bo    = (const float*)d_in[8];
    float* out = (float*)d_out;

    __half *keyh, *valh, *qh, *wvh, *wkT, *woT, *wvoT, *kproj, *vprT2, *sc;
    float *bvo;
    cudaGetSymbolAddress((void**)&keyh,  g_keyh);
    cudaGetSymbolAddress((void**)&valh,  g_valh);
    cudaGetSymbolAddress((void**)&qh,    g_qh);
    cudaGetSymbolAddress((void**)&wvh,   g_wvh);
    cudaGetSymbolAddress((void**)&wkT,   g_wkT);
    cudaGetSymbolAddress((void**)&woT,   g_woT);
    cudaGetSymbolAddress((void**)&wvoT,  g_wvoT);
    cudaGetSymbolAddress((void**)&bvo,   g_bvo);
    cudaGetSymbolAddress((void**)&kproj, g_kproj);
    cudaGetSymbolAddress((void**)&vprT2, g_vprT2);
    cudaGetSymbolAddress((void**)&sc,    g_sc);

    static bool attr_done = false;
    if (!attr_done) {
        cudaFuncSetAttribute(gemm256<true, false>,
                             cudaFuncAttributeMaxDynamicSharedMemorySize, A_SMEM);
        cudaFuncSetAttribute(gemm256<true, true>,
                             cudaFuncAttributeMaxDynamicSharedMemorySize, A_SMEM);
        cudaFuncSetAttribute(gemm256<false, false>,
                             cudaFuncAttributeMaxDynamicSharedMemorySize, A_SMEM);
        attr_done = true;
    }

    const float scale = 1.0f / sqrtf((float)D_Q);

    // 0) prep: fp16 conversions (scale folded into Q; Wv plain convert),
    //    transposes of Wk/Wo, and bvo = Wo^T bv.
    prep_convert<<<2048, 256>>>(keyh, key, valh, value, qh, query, wvh, Wv,
                                MKV * D_C / 8, BATCH * L_Q * D_Q / 8,
                                D_C * D_Q / 8, scale);
    prep_transpose<<<642, 256>>>(wkT, Wk, woT, Wo, bvo, bv);

    // 0b) WvoT[512,768] = (Wv@Wo)^T: NT GEMM A=woT[512,512], B=wvh[768,512].
    gemm256<true, false><<<dim3(D_C / 256, D_Q / 128, 1), 256, A_SMEM>>>(
        woT, wvh, wvoT, nullptr, D_Q, D_C, D_Q, D_Q, D_Q, D_C, 0, 0, 0);

    // 1) K projection: kproj[16384,512] = keyh @ wkT^T + bk (col bias).
    gemm256<true, false><<<dim3(D_Q / 256, MKV / 128, 1), 256, A_SMEM>>>(
        keyh, wkT, kproj, bk, MKV, D_Q, D_C, D_C, D_C, D_Q, 0, 0, 0);

    // 2) Folded V projection TRANSPOSED: vprT2[512,16384] = wvoT @ valh^T + bvo
    //    (row bias). vprT2 = (V@Wv@Wo + 1*(Wo^T bv)^T)^T.
    gemm256<true, true><<<dim3(MKV / 256, D_Q / 128, 1), 256, A_SMEM>>>(
        wvoT, valh, vprT2, bvo, D_Q, MKV, D_C, D_C, D_C, MKV, 0, 0, 0);

    // 3) Scores per batch: qh_b[2048,512] @ kproj_b^T -> fp16 (scale pre-folded).
    gemm256<true, false><<<dim3(L_KV / 256, L_Q / 128, BATCH), 256, A_SMEM>>>(
        qh, kproj, sc, nullptr, L_Q, L_KV, D_Q, D_Q, D_Q, L_KV,
        (long)L_Q * D_Q, (long)L_KV * D_Q, (long)L_Q * L_KV);

    // 4) Softmax in place (fp16).
    softmax_h2048<<<BATCH * L_Q, 256>>>(sc);

    // 5) Final: out_b[2048,512] = probs_b @ (vprT2[:, b])^T + bo (col bias), fp32.
    gemm256<false, false><<<dim3(D_Q / 256, L_Q / 128, BATCH), 256, A_SMEM>>>(
        sc, vprT2, out, bo, L_Q, D_Q, L_KV, L_KV, MKV, D_Q,
        (long)L_Q * L_KV, (long)L_KV, (long)L_Q * D_Q);
}

// round 17
// speedup vs baseline: 1.0960x; 1.0577x over previous
#include <cuda_runtime.h>
#include <cuda_fp16.h>
#include <cstdint>

// ---------------------------------------------------------------------------
// CrossAttention via fp16 mma.sync.m16n8k16 (fp32 accumulate) NT GEMMs.
// Round 17: stream-level overlap. Side chain (prep_transpose -> Wvo -> vprT2)
// runs concurrently with main chain (prep_convert -> kproj -> scores ->
// softmax); join before the final GEMM. Kernels identical to round 16.
//   out = P@(V@(Wv@Wo) + 1*(Wo^T bv)^T) + bo
// ---------------------------------------------------------------------------

#define BATCH 8
#define L_Q   2048
#define L_KV  2048
#define D_Q   512
#define D_C   768
#define MKV   (BATCH * L_KV)   // 16384

// Scratch (device globals).
__device__ __align__(128) __half g_keyh [MKV * D_C];
__device__ __align__(128) __half g_valh [MKV * D_C];
__device__ __align__(128) __half g_qh   [BATCH * L_Q * D_Q];
__device__ __align__(128) __half g_wvh  [D_C * D_Q];              // Wv fp16 (row-major)
__device__ __align__(128) __half g_wkT  [D_Q * D_C];
__device__ __align__(128) __half g_woT  [D_Q * D_Q];
__device__ __align__(128) __half g_wvoT [D_Q * D_C];              // (Wv@Wo)^T
__device__ __align__(128) float  g_bvo  [D_Q];                    // Wo^T bv
__device__ __align__(128) __half g_kproj[MKV * D_Q];
__device__ __align__(128) __half g_vprT2[D_Q * MKV];              // (V@Wvo + bvo)^T
__device__ __align__(128) __half g_sc   [(size_t)BATCH * L_Q * L_KV]; // scores/probs

// ---------------------------------------------------------------------------
// PTX helpers
// ---------------------------------------------------------------------------
__device__ __forceinline__ uint32_t smem_u32(const void* p) {
    uint32_t a;
    asm("{ .reg .u64 t; cvta.to.shared.u64 t, %1; cvt.u32.u64 %0, t; }"
        : "=r"(a) : "l"(p));
    return a;
}
__device__ __forceinline__ void cp16(uint32_t s, const void* g) {
    asm volatile("cp.async.cg.shared.global [%0], [%1], 16;" :: "r"(s), "l"(g));
}
#define CP_COMMIT()  asm volatile("cp.async.commit_group;")
#define CP_WAIT(n)   asm volatile("cp.async.wait_group %0;" :: "n"(n))

__device__ __forceinline__ void ldsm_x4(uint32_t r[4], uint32_t addr) {
    asm volatile("ldmatrix.sync.aligned.m8n8.x4.shared.b16 {%0,%1,%2,%3}, [%4];"
                 : "=r"(r[0]), "=r"(r[1]), "=r"(r[2]), "=r"(r[3]) : "r"(addr));
}
__device__ __forceinline__ void mma_f16(float c[4], const uint32_t a[4],
                                        uint32_t b0, uint32_t b1) {
    asm volatile(
        "mma.sync.aligned.m16n8k16.row.col.f32.f16.f16.f32 "
        "{%0,%1,%2,%3}, {%4,%5,%6,%7}, {%8,%9}, {%0,%1,%2,%3};"
        : "+f"(c[0]), "+f"(c[1]), "+f"(c[2]), "+f"(c[3])
        : "r"(a[0]), "r"(a[1]), "r"(a[2]), "r"(a[3]), "r"(b0), "r"(b1));
}

// ===========================================================================
// NT GEMM: C[M,N] = A[M,K] @ B[N,K]^T (+ bias).
// BM=128, BN=256, BK=128, 256 thr (8 warps 2x4, warp tile 64x64).
// 2-stage cp.async (204KB smem), fragment double-buffering.
// ===========================================================================
#define ROWB 272                       // bytes per smem row (136 halves)
#define A_STGA (128 * ROWB)            // 34816
#define A_STGB (256 * ROWB)            // 69632
#define A_STG  (A_STGA + A_STGB)       // 104448
#define A_SMEM (2 * A_STG)             // 208896

template <bool OUT_HALF, bool ROWBIAS>
__global__ void __launch_bounds__(256, 1)
gemm256(const __half* __restrict__ A, const __half* __restrict__ B,
        void* __restrict__ Cv, const float* __restrict__ bias,
        int M, int N, int K, int ldA, int ldB, int ldC,
        long sA, long sB, long sC)
{
    extern __shared__ char smem[];
    const uint32_t sbase = smem_u32(smem);

    const int tid  = threadIdx.x;
    const int lane = tid & 31;
    const int warp = tid >> 5;
    const int g = lane >> 2;
    const int t = lane & 3;
    const int mw = (warp >> 2) * 64;
    const int nw = (warp & 3) * 64;

    const int bm = blockIdx.y * 128;
    const int bn = blockIdx.x * 256;
    A += (long)blockIdx.z * sA;
    B += (long)blockIdx.z * sB;

    const int cu = tid & 15;
    const int r0 = tid >> 4;

    const int nk = K / 128;

    auto load_tile = [&](int kt) {
        const int s = kt & 1;
        const uint32_t as = sbase + s * A_STG;
        const uint32_t bs = as + A_STGA;
        const long kof = (long)kt * 128 + cu * 8;
        #pragma unroll
        for (int i = 0; i < 8; i++) {
            const int r = r0 + 16 * i;
            cp16(as + r * ROWB + cu * 16, A + (long)(bm + r) * ldA + kof);
        }
        #pragma unroll
        for (int i = 0; i < 16; i++) {
            const int r = r0 + 16 * i;
            cp16(bs + r * ROWB + cu * 16, B + (long)(bn + r) * ldB + kof);
        }
        CP_COMMIT();
    };

    float acc[4][8][4];
    #pragma unroll
    for (int i = 0; i < 4; i++)
        #pragma unroll
        for (int j = 0; j < 8; j++)
            #pragma unroll
            for (int r = 0; r < 4; r++) acc[i][j][r] = 0.0f;

    load_tile(0);

    const int lrow = lane & 15;
    const int lkb  = (lane >> 4) * 16;
    uint32_t aoff[4], boff[4];
    #pragma unroll
    for (int i = 0; i < 4; i++)  aoff[i]  = (mw + 16 * i + lrow) * ROWB + lkb;
    #pragma unroll
    for (int jj = 0; jj < 4; jj++) boff[jj] = (nw + 16 * jj + lrow) * ROWB + lkb;

    uint32_t a[2][4][4], b[2][4][4];

    for (int kt = 0; kt < nk; kt++) {
        if (kt + 1 < nk) { load_tile(kt + 1); CP_WAIT(1); }
        else             { CP_WAIT(0); }
        __syncthreads();

        const int s = kt & 1;
        const uint32_t as = sbase + s * A_STG;
        const uint32_t bs = as + A_STGA;

        #pragma unroll
        for (int i = 0; i < 4; i++)  ldsm_x4(a[0][i], as + aoff[i]);
        #pragma unroll
        for (int jj = 0; jj < 4; jj++) ldsm_x4(b[0][jj], bs + boff[jj]);

        #pragma unroll
        for (int kh = 0; kh < 8; kh++) {
            const int cur = kh & 1, nxt = cur ^ 1;
            if (kh < 7) {
                #pragma unroll
                for (int i = 0; i < 4; i++)
                    ldsm_x4(a[nxt][i], as + aoff[i] + (kh + 1) * 32);
                #pragma unroll
                for (int jj = 0; jj < 4; jj++)
                    ldsm_x4(b[nxt][jj], bs + boff[jj] + (kh + 1) * 32);
            }
            #pragma unroll
            for (int i = 0; i < 4; i++) {
                #pragma unroll
                for (int jj = 0; jj < 4; jj++) {
                    mma_f16(acc[i][2 * jj + 0], a[cur][i], b[cur][jj][0], b[cur][jj][2]);
                    mma_f16(acc[i][2 * jj + 1], a[cur][i], b[cur][jj][1], b[cur][jj][3]);
                }
            }
        }
        __syncthreads();
    }

    #pragma unroll
    for (int i = 0; i < 4; i++) {
        const int r = bm + mw + 16 * i + g;
        float brow0 = 0.0f, brow1 = 0.0f;
        if (ROWBIAS && bias) { brow0 = bias[r]; brow1 = bias[r + 8]; }
        #pragma unroll
        for (int j = 0; j < 8; j++) {
            const int c = bn + nw + 8 * j + 2 * t;
            float bc0 = 0.0f, bc1 = 0.0f;
            if (!ROWBIAS && bias) { bc0 = bias[c]; bc1 = bias[c + 1]; }
            const float v00 = acc[i][j][0] + (ROWBIAS ? brow0 : bc0);
            const float v01 = acc[i][j][1] + (ROWBIAS ? brow0 : bc1);
            const float v10 = acc[i][j][2] + (ROWBIAS ? brow1 : bc0);
            const float v11 = acc[i][j][3] + (ROWBIAS ? brow1 : bc1);
            if (OUT_HALF) {
                __half* C = (__half*)Cv + (long)blockIdx.z * sC;
                *(__half2*)(C + (long)r * ldC + c)       = __floats2half2_rn(v00, v01);
                *(__half2*)(C + (long)(r + 8) * ldC + c) = __floats2half2_rn(v10, v11);
            } else {
                float* C = (float*)Cv + (long)blockIdx.z * sC;
                *(float2*)(C + (long)r * ldC + c)       = make_float2(v00, v01);
                *(float2*)(C + (long)(r + 8) * ldC + c) = make_float2(v10, v11);
            }
        }
    }
}

// ---------------------------------------------------------------------------
// Merged conversion: key, value, q (scaled), Wv. Grid-stride over 16B chunks.
// ---------------------------------------------------------------------------
__global__ void __launch_bounds__(256)
prep_convert(__half* __restrict__ keyh, const float* __restrict__ key,
             __half* __restrict__ valh, const float* __restrict__ value,
             __half* __restrict__ qh,   const float* __restrict__ query,
             __half* __restrict__ wvh,  const float* __restrict__ Wv,
             int n8k, int n8q, int n8w, float qscale)
{
    const int total = 2 * n8k + n8q + n8w;
    for (int i = blockIdx.x * blockDim.x + threadIdx.x; i < total;
         i += gridDim.x * blockDim.x) {
        const float* src; __half* dst; int idx; float sc = 1.0f;
        if (i < n8k)                  { src = key;   dst = keyh; idx = i; }
        else if (i < 2 * n8k)         { src = value; dst = valh; idx = i - n8k; }
        else if (i < 2 * n8k + n8q)   { src = query; dst = qh;   idx = i - 2 * n8k; sc = qscale; }
        else                          { src = Wv;    dst = wvh;  idx = i - 2 * n8k - n8q; }
        float4 v0 = ((const float4*)src)[2 * idx];
        float4 v1 = ((const float4*)src)[2 * idx + 1];
        __half2 h[4];
        h[0] = __floats2half2_rn(v0.x * sc, v0.y * sc);
        h[1] = __floats2half2_rn(v0.z * sc, v0.w * sc);
        h[2] = __floats2half2_rn(v1.x * sc, v1.y * sc);
        h[3] = __floats2half2_rn(v1.z * sc, v1.w * sc);
        ((uint4*)dst)[idx] = *(uint4*)h;
    }
}

// ---------------------------------------------------------------------------
// Merged weight transposes: Wk[768,512]->wkT[512,768], Wo[512,512]->woT.
// Plus bvo[n] = sum_d bv[d]*Wo[d][n] (blocks 640..641).
// ---------------------------------------------------------------------------
__global__ void __launch_bounds__(256)
prep_transpose(__half* __restrict__ wkT, const float* __restrict__ Wk,
               __half* __restrict__ woT, const float* __restrict__ Wo,
               float* __restrict__ bvo,  const float* __restrict__ bv)
{
    int b = blockIdx.x;
    if (b >= 640) {            // bvo: 2 blocks x 256 threads = 512 outputs
        const int n = (b - 640) * 256 + threadIdx.x;
        float s = 0.0f;
        for (int d = 0; d < D_Q; d++)
            s += bv[d] * Wo[(long)d * D_Q + n];
        bvo[n] = s;
        return;
    }
    const float* src; __half* dst; int K, N;
    if (b < 384)       { src = Wk; dst = wkT; K = D_C; N = D_Q; }
    else               { src = Wo; dst = woT; K = D_Q; N = D_Q; b -= 384; }
    const int ntx = N / 32;
    const int n0 = (b % ntx) * 32;
    const int k0 = (b / ntx) * 32;

    __shared__ float tile[32][33];
    const int tx = threadIdx.x & 31;
    const int ty = threadIdx.x >> 5;
    #pragma unroll
    for (int i = 0; i < 32; i += 8)
        tile[ty + i][tx] = src[(long)(k0 + ty + i) * N + n0 + tx];
    __syncthreads();
    #pragma unroll
    for (int i = 0; i < 32; i += 8)
        dst[(long)(n0 + ty + i) * K + k0 + tx] = __float2half(tile[tx][ty + i]);
}

// ---------------------------------------------------------------------------
// In-place row softmax over 2048-length rows, fp16 in / fp16 out.
// ---------------------------------------------------------------------------
__global__ void __launch_bounds__(256)
softmax_h2048(__half* __restrict__ S)
{
    __half2* p = (__half2*)(S + (size_t)blockIdx.x * 2048);
    const int t = threadIdx.x;

    float v[8];
    #pragma unroll
    for (int i = 0; i < 4; i++) {
        float2 f = __half22float2(p[t + i * 256]);
        v[2 * i] = f.x; v[2 * i + 1] = f.y;
    }
    float mx = -1e30f;
    #pragma unroll
    for (int i = 0; i < 8; i++) mx = fmaxf(mx, v[i]);

    __shared__ float red[8];
    #pragma unroll
    for (int o = 16; o > 0; o >>= 1)
        mx = fmaxf(mx, __shfl_xor_sync(0xFFFFFFFFu, mx, o));
    if ((t & 31) == 0) red[t >> 5] = mx;
    __syncthreads();
    float rowmax = red[0];
    #pragma unroll
    for (int w = 1; w < 8; w++) rowmax = fmaxf(rowmax, red[w]);
    __syncthreads();

    float sum = 0.0f;
    #pragma unroll
    for (int i = 0; i < 8; i++) {
        v[i] = __expf(v[i] - rowmax);
        sum += v[i];
    }
    #pragma unroll
    for (int o = 16; o > 0; o >>= 1)
        sum += __shfl_xor_sync(0xFFFFFFFFu, sum, o);
    if ((t & 31) == 0) red[t >> 5] = sum;
    __syncthreads();
    float rowsum = 0.0f;
    #pragma unroll
    for (int w = 0; w < 8; w++) rowsum += red[w];

    const float inv = 1.0f / rowsum;
    #pragma unroll
    for (int i = 0; i < 4; i++)
        p[t + i * 256] = __floats2half2_rn(v[2 * i] * inv, v[2 * i + 1] * inv);
}

// ---------------------------------------------------------------------------
// Launcher — fork/join stream DAG (graph-capture-safe event pattern).
// ---------------------------------------------------------------------------
extern "C" void kernel_launch(void* const* d_in, const int* in_sizes, int n_in,
                              void* d_out, int out_size)
{
    const float* query = (const float*)d_in[0];
    const float* key   = (const float*)d_in[1];
    const float* value = (const float*)d_in[2];
    const float* Wk    = (const float*)d_in[3];
    const float* bk    = (const float*)d_in[4];
    const float* Wv    = (const float*)d_in[5];
    const float* bv    = (const float*)d_in[6];
    const float* Wo    = (const float*)d_in[7];
    const float* bo    = (const float*)d_in[8];
    float* out = (float*)d_out;

    __half *keyh, *valh, *qh, *wvh, *wkT, *woT, *wvoT, *kproj, *vprT2, *sc;
    float *bvo;
    cudaGetSymbolAddress((void**)&keyh,  g_keyh);
    cudaGetSymbolAddress((void**)&valh,  g_valh);
    cudaGetSymbolAddress((void**)&qh,    g_qh);
    cudaGetSymbolAddress((void**)&wvh,   g_wvh);
    cudaGetSymbolAddress((void**)&wkT,   g_wkT);
    cudaGetSymbolAddress((void**)&woT,   g_woT);
    cudaGetSymbolAddress((void**)&wvoT,  g_wvoT);
    cudaGetSymbolAddress((void**)&bvo,   g_bvo);
    cudaGetSymbolAddress((void**)&kproj, g_kproj);
    cudaGetSymbolAddress((void**)&vprT2, g_vprT2);
    cudaGetSymbolAddress((void**)&sc,    g_sc);

    static bool init_done = false;
    static cudaStream_t side = nullptr;
    static cudaEvent_t ev_fork, ev_conv, ev_tr, ev_side;
    if (!init_done) {
        cudaFuncSetAttribute(gemm256<true, false>,
                             cudaFuncAttributeMaxDynamicSharedMemorySize, A_SMEM);
        cudaFuncSetAttribute(gemm256<true, true>,
                             cudaFuncAttributeMaxDynamicSharedMemorySize, A_SMEM);
        cudaFuncSetAttribute(gemm256<false, false>,
                             cudaFuncAttributeMaxDynamicSharedMemorySize, A_SMEM);
        cudaStreamCreateWithFlags(&side, cudaStreamNonBlocking);
        cudaEventCreateWithFlags(&ev_fork, cudaEventDisableTiming);
        cudaEventCreateWithFlags(&ev_conv, cudaEventDisableTiming);
        cudaEventCreateWithFlags(&ev_tr,   cudaEventDisableTiming);
        cudaEventCreateWithFlags(&ev_side, cudaEventDisableTiming);
        init_done = true;
    }

    const float scale = 1.0f / sqrtf((float)D_Q);

    // ---- fork ----
    cudaEventRecord(ev_fork, 0);
    cudaStreamWaitEvent(side, ev_fork, 0);

    // main: conversions (key/value/q/Wv).   side: transposes + bvo.
    prep_convert<<<2048, 256>>>(keyh, key, valh, value, qh, query, wvh, Wv,
                                MKV * D_C / 8, BATCH * L_Q * D_Q / 8,
                                D_C * D_Q / 8, scale);
    prep_transpose<<<642, 256, 0, side>>>(wkT, Wk, woT, Wo, bvo, bv);

    cudaEventRecord(ev_conv, 0);          // convert done (keyh/valh/qh/wvh)
    cudaEventRecord(ev_tr, side);         // transpose done (wkT/woT/bvo)

    cudaStreamWaitEvent(0, ev_tr, 0);     // main needs wkT for kproj
    cudaStreamWaitEvent(side, ev_conv, 0);// side needs wvh/valh

    // side chain: WvoT[512,768] = (Wv@Wo)^T, then folded V projection.
    gemm256<true, false><<<dim3(D_C / 256, D_Q / 128, 1), 256, A_SMEM, side>>>(
        woT, wvh, wvoT, nullptr, D_Q, D_C, D_Q, D_Q, D_Q, D_C, 0, 0, 0);
    gemm256<true, true><<<dim3(MKV / 256, D_Q / 128, 1), 256, A_SMEM, side>>>(
        wvoT, valh, vprT2, bvo, D_Q, MKV, D_C, D_C, D_C, MKV, 0, 0, 0);
    cudaEventRecord(ev_side, side);

    // main chain: kproj -> scores -> softmax.
    gemm256<true, false><<<dim3(D_Q / 256, MKV / 128, 1), 256, A_SMEM>>>(
        keyh, wkT, kproj, bk, MKV, D_Q, D_C, D_C, D_C, D_Q, 0, 0, 0);
    gemm256<true, false><<<dim3(L_KV / 256, L_Q / 128, BATCH), 256, A_SMEM>>>(
        qh, kproj, sc, nullptr, L_Q, L_KV, D_Q, D_Q, D_Q, L_KV,
        (long)L_Q * D_Q, (long)L_KV * D_Q, (long)L_Q * L_KV);
    softmax_h2048<<<BATCH * L_Q, 256>>>(sc);

    // ---- join, then final: out = probs @ vprT2^T + bo (fp32). ----
    cudaStreamWaitEvent(0, ev_side, 0);
    gemm256<false, false><<<dim3(D_Q / 256, L_Q / 128, BATCH), 256, A_SMEM>>>(
        sc, vprT2, out, bo, L_Q, D_Q, L_KV, L_KV, MKV, D_Q,
        (long)L_Q * L_KV, (long)L_KV, (long)L_Q * D_Q);
}